// round 10
// baseline (speedup 1.0000x reference)
#include <cuda_runtime.h>

// out[r, c] = x[r, c] * weight[c]   for x: [32768, 1024] fp32, weight: [1024] fp32
//
// R10: final roofline config (R2: 256 thr, 8x float4 front-batched, hoisted
// weight) with ONE micro-probe left untested: __stwt (write-through) stores
// instead of __stcs. Theory: avoid L2 dirty-line tail-drain serializing with
// the read stream; expected neutral-to-tiny-win. Everything else identical
// to the thrice-replicated 43.5-43.8us / 7.5 TB/s kernel.

static constexpr int ROWS = 32768;
static constexpr int COLS = 1024;
static constexpr unsigned N_VEC4 = (unsigned)ROWS * (COLS / 4);   // 8,388,608
static constexpr int THREADS = 256;
static constexpr int VEC_PER_THREAD = 8;
static constexpr int BLOCKS = (int)(N_VEC4 / (THREADS * VEC_PER_THREAD)); // 4096
static constexpr int COLS_VEC4 = COLS / 4;                        // 256
static_assert(THREADS == COLS_VEC4, "weight-hoist relies on THREADS == COLS/4");
static_assert((unsigned)BLOCKS * THREADS * VEC_PER_THREAD == N_VEC4, "exact cover");

__global__ __launch_bounds__(THREADS)
void diag_weight_kernel(const float4* __restrict__ x,
                        const float4* __restrict__ w,
                        float4* __restrict__ out) {
    const unsigned tid = threadIdx.x;
    const unsigned base = blockIdx.x * (unsigned)(THREADS * VEC_PER_THREAD) + tid;

    // One weight vector per thread: every index this thread touches is
    // congruent to tid (mod 256). 4 KiB table -> L1-resident after warmup.
    const float4 vw = w[tid];

    float4 vx[VEC_PER_THREAD];

    // Front-batch all 8 streaming loads (MLP burst = 8 per thread; x is
    // single-touch, evict-first).
#pragma unroll
    for (int i = 0; i < VEC_PER_THREAD; i++) {
        vx[i] = __ldcs(&x[base + (unsigned)i * THREADS]);
    }

#pragma unroll
    for (int i = 0; i < VEC_PER_THREAD; i++) {
        float4 r;
        r.x = vx[i].x * vw.x;
        r.y = vx[i].y * vw.y;
        r.z = vx[i].z * vw.z;
        r.w = vx[i].w * vw.w;
        __stwt(&out[base + (unsigned)i * THREADS], r);  // write-through probe
    }
}

extern "C" void kernel_launch(void* const* d_in, const int* in_sizes, int n_in,
                              void* d_out, int out_size) {
    const float4* x = (const float4*)d_in[0];   // [32768, 1024] fp32
    const float4* w = (const float4*)d_in[1];   // [1024] fp32
    float4* out = (float4*)d_out;

    diag_weight_kernel<<<BLOCKS, THREADS>>>(x, w, out);
}

// round 11
// speedup vs baseline: 1.0360x; 1.0360x over previous
#include <cuda_runtime.h>

// out[r, c] = x[r, c] * weight[c]   for x: [32768, 1024] fp32, weight: [1024] fp32
//
// FINAL — machine-roofline kernel (R2 config; best measured: 43.5us timed,
// 35.74us in-window = 7.5 TB/s ~ 94% of 8 TB/s HBM spec).
//
// Closed-out session evidence (10 rounds):
// - Traffic floor 268 MB is irreducible (fp32 in/out, exact elementwise op).
// - One-shot fine-grained CTAs win: HW overlaps dying CTAs' store drain with
//   fresh CTAs' front-batched loads for free.
// - Persistent kernels lose (chunk-boundary drains R6; double-buffer demoted
//   to local memory R7). Fat CTAs lose (register bloat R4).
// - Occupancy 32-77%, MLP 4-8, 128/256/512-thread CTAs, __stcs vs __stwt:
//   all within +-2%. The DRAM sink is the binding constraint.
// - Timed = in-window + ~7.8us fixed graph-replay overhead.

static constexpr int ROWS = 32768;
static constexpr int COLS = 1024;
static constexpr unsigned N_VEC4 = (unsigned)ROWS * (COLS / 4);   // 8,388,608
static constexpr int THREADS = 256;
static constexpr int VEC_PER_THREAD = 8;
static constexpr int BLOCKS = (int)(N_VEC4 / (THREADS * VEC_PER_THREAD)); // 4096
static constexpr int COLS_VEC4 = COLS / 4;                        // 256
static_assert(THREADS == COLS_VEC4, "weight-hoist relies on THREADS == COLS/4");
static_assert((unsigned)BLOCKS * THREADS * VEC_PER_THREAD == N_VEC4, "exact cover");

__global__ __launch_bounds__(THREADS)
void diag_weight_kernel(const float4* __restrict__ x,
                        const float4* __restrict__ w,
                        float4* __restrict__ out) {
    const unsigned tid = threadIdx.x;
    // Block covers a contiguous span of THREADS*VEC_PER_THREAD float4s;
    // iteration i is offset by i*THREADS (fully coalesced).
    const unsigned base = blockIdx.x * (unsigned)(THREADS * VEC_PER_THREAD) + tid;

    // One weight vector per thread: every index this thread touches is
    // congruent to tid (mod 256). 4 KiB table -> L1-resident after warmup.
    const float4 vw = w[tid];

    float4 vx[VEC_PER_THREAD];

    // Front-batch all 8 streaming loads (MLP burst = 8 per thread; x is
    // single-touch, 256 MB >> 126 MB L2, so evict-first).
#pragma unroll
    for (int i = 0; i < VEC_PER_THREAD; i++) {
        vx[i] = __ldcs(&x[base + (unsigned)i * THREADS]);
    }

#pragma unroll
    for (int i = 0; i < VEC_PER_THREAD; i++) {
        float4 r;
        r.x = vx[i].x * vw.x;
        r.y = vx[i].y * vw.y;
        r.z = vx[i].z * vw.z;
        r.w = vx[i].w * vw.w;
        __stcs(&out[base + (unsigned)i * THREADS], r);
    }
}

extern "C" void kernel_launch(void* const* d_in, const int* in_sizes, int n_in,
                              void* d_out, int out_size) {
    const float4* x = (const float4*)d_in[0];   // [32768, 1024] fp32
    const float4* w = (const float4*)d_in[1];   // [1024] fp32
    float4* out = (float4*)d_out;

    diag_weight_kernel<<<BLOCKS, THREADS>>>(x, w, out);
}